// round 13
// baseline (speedup 1.0000x reference)
#include <cuda_runtime.h>
#include <cstdint>
#include <math.h>

#define BATCH   2
#define S_LEN   2048
#define HEADS   16
#define HD      64
#define DM      1024
#define M_TOT   (BATCH * S_LEN)          // 4096

// ---------------- scratch (device globals: allocation-free) ----------------
__device__ float g_q[BATCH * HEADS * S_LEN * HD];    // [B,H,S,64]
__device__ float g_k[BATCH * HEADS * S_LEN * HD];
__device__ float g_v[BATCH * HEADS * S_LEN * HD];
__device__ float g_cat[BATCH * S_LEN * DM];          // [B,S,H*64]

// ---------------- common tf32 helpers --------------------------------------
__device__ __forceinline__ unsigned f2tf(float x) {
    unsigned r;
    asm("cvt.rna.tf32.f32 %0, %1;" : "=r"(r) : "f"(x));
    return r;
}

__device__ __forceinline__ void mma_tf32(float* c, const unsigned* a, const unsigned* b) {
    asm volatile(
        "mma.sync.aligned.m16n8k8.row.col.f32.tf32.tf32.f32 "
        "{%0,%1,%2,%3}, {%4,%5,%6,%7}, {%8,%9}, {%0,%1,%2,%3};\n"
        : "+f"(c[0]), "+f"(c[1]), "+f"(c[2]), "+f"(c[3])
        : "r"(a[0]), "r"(a[1]), "r"(a[2]), "r"(a[3]), "r"(b[0]), "r"(b[1]));
}

__device__ __forceinline__ float ex2(float x) {
    float r;
    asm("ex2.approx.f32 %0, %1;" : "=f"(r) : "f"(x));
    return r;
}

// ---------------- tf32 tensor-core GEMM (mma.sync, double-buffered) --------
// C[M,N] = A[M,K] * W[N,K]^T + bias; CTA 128x128, BK=32, 8 warps, warp 64x32.
#define LDA 36
#define BUF_W (128 * LDA)      // words per operand buffer (4608)
#define GEMM_SMEM (4 * BUF_W * 4)   // 73728 bytes: A0,W0,A1,W1

__device__ __forceinline__ void gemm_body(
    const float* __restrict__ A, const float* __restrict__ W,
    const float* __restrict__ bias, float* __restrict__ C, int scatter)
{
    extern __shared__ __align__(16) unsigned gsm[];
    unsigned* Abuf[2] = { gsm,            gsm + 2 * BUF_W };
    unsigned* Wbuf[2] = { gsm + BUF_W,    gsm + 3 * BUF_W };

    const int tid  = threadIdx.x;
    const int lane = tid & 31;
    const int wid  = tid >> 5;
    const int wm   = wid >> 2;
    const int wn   = wid & 3;
    const int bm   = blockIdx.y * 128;
    const int bn   = blockIdx.x * 128;

    const int grp = lane >> 2;
    const int tig = lane & 3;

    const int lrow = tid >> 1;             // 0..127
    const int lcol = (tid & 1) * 16;       // 0 or 16
    const int idx4 = lrow * 9 + (lcol >> 2);   // uint4 index into buffer

    const float* Ap = A + (size_t)(bm + lrow) * DM + lcol;
    const float* Wp = W + (size_t)(bn + lrow) * DM + lcol;

    float c[4][4][4];
#pragma unroll
    for (int i = 0; i < 4; i++)
#pragma unroll
        for (int j = 0; j < 4; j++)
#pragma unroll
            for (int r = 0; r < 4; r++) c[i][j][r] = 0.f;

    float4 pa[4], pw[4];
    // chunk 0 prefetch + stage into buffer 0
#pragma unroll
    for (int u = 0; u < 4; u++) {
        pa[u] = *(const float4*)(Ap + u * 4);
        pw[u] = *(const float4*)(Wp + u * 4);
    }
    {
        uint4* a4 = (uint4*)Abuf[0] + idx4;
        uint4* w4 = (uint4*)Wbuf[0] + idx4;
#pragma unroll
        for (int u = 0; u < 4; u++) {
            a4[u] = make_uint4(f2tf(pa[u].x), f2tf(pa[u].y), f2tf(pa[u].z), f2tf(pa[u].w));
            w4[u] = make_uint4(f2tf(pw[u].x), f2tf(pw[u].y), f2tf(pw[u].z), f2tf(pw[u].w));
        }
    }
    __syncthreads();

    for (int kt = 0; kt < 32; kt++) {
        const int cur = kt & 1;
        const unsigned* As = Abuf[cur];
        const unsigned* Ws = Wbuf[cur];

        // prefetch next chunk from global while mma runs
        if (kt + 1 < 32) {
#pragma unroll
            for (int u = 0; u < 4; u++) {
                pa[u] = *(const float4*)(Ap + (kt + 1) * 32 + u * 4);
                pw[u] = *(const float4*)(Wp + (kt + 1) * 32 + u * 4);
            }
        }

#pragma unroll
        for (int ks = 0; ks < 4; ks++) {
            unsigned b[4][2];
#pragma unroll
            for (int j = 0; j < 4; j++) {
                int n = wn * 32 + j * 8 + grp;
                int k = ks * 8 + tig;
                b[j][0] = Ws[n * LDA + k];
                b[j][1] = Ws[n * LDA + k + 4];
            }
#pragma unroll
            for (int i = 0; i < 4; i++) {
                unsigned a[4];
                int m = wm * 64 + i * 16 + grp;
                int k = ks * 8 + tig;
                a[0] = As[m * LDA + k];
                a[1] = As[(m + 8) * LDA + k];
                a[2] = As[m * LDA + k + 4];
                a[3] = As[(m + 8) * LDA + k + 4];
#pragma unroll
                for (int j = 0; j < 4; j++)
                    mma_tf32(c[i][j], a, b[j]);
            }
        }

        // stage next chunk into the other buffer (readers of it synced last iter)
        if (kt + 1 < 32) {
            uint4* a4 = (uint4*)Abuf[cur ^ 1] + idx4;
            uint4* w4 = (uint4*)Wbuf[cur ^ 1] + idx4;
#pragma unroll
            for (int u = 0; u < 4; u++) {
                a4[u] = make_uint4(f2tf(pa[u].x), f2tf(pa[u].y), f2tf(pa[u].z), f2tf(pa[u].w));
                w4[u] = make_uint4(f2tf(pw[u].x), f2tf(pw[u].y), f2tf(pw[u].z), f2tf(pw[u].w));
            }
        }
        __syncthreads();
    }

    // epilogue: bias + store
#pragma unroll
    for (int j = 0; j < 4; j++) {
        int n0 = bn + wn * 32 + j * 8 + 2 * tig;
        float bia0 = bias[n0];
        float bia1 = bias[n0 + 1];
#pragma unroll
        for (int i = 0; i < 4; i++) {
            int m0 = bm + wm * 64 + i * 16 + grp;
            float2 v0 = make_float2(c[i][j][0] + bia0, c[i][j][1] + bia1);
            float2 v1 = make_float2(c[i][j][2] + bia0, c[i][j][3] + bia1);
            if (scatter) {
                int h = n0 >> 6, d = n0 & 63;
                int b0 = m0 >> 11, s0 = m0 & 2047;
                int b1 = (m0 + 8) >> 11, s1 = (m0 + 8) & 2047;
                *(float2*)&C[(((size_t)b0 * HEADS + h) * S_LEN + s0) * HD + d] = v0;
                *(float2*)&C[(((size_t)b1 * HEADS + h) * S_LEN + s1) * HD + d] = v1;
            } else {
                *(float2*)&C[(size_t)m0 * DM + n0] = v0;
                *(float2*)&C[(size_t)(m0 + 8) * DM + n0] = v1;
            }
        }
    }
}

// merged QKV projection: z selects Q/K/V weights+output
__global__ __launch_bounds__(256) void gemm_qkv(
    const float* __restrict__ x,
    const float* __restrict__ Wq, const float* __restrict__ bq, float* __restrict__ Oq,
    const float* __restrict__ Wk, const float* __restrict__ bk, float* __restrict__ Ok,
    const float* __restrict__ Wv, const float* __restrict__ bv, float* __restrict__ Ov)
{
    int z = blockIdx.z;
    const float* W = (z == 0) ? Wq : (z == 1) ? Wk : Wv;
    const float* bb = (z == 0) ? bq : (z == 1) ? bk : bv;
    float* O = (z == 0) ? Oq : (z == 1) ? Ok : Ov;
    gemm_body(x, W, bb, O, 1);
}

__global__ __launch_bounds__(256) void gemm_out(
    const float* __restrict__ A, const float* __restrict__ W,
    const float* __restrict__ bias, float* __restrict__ C)
{
    gemm_body(A, W, bias, C, 0);
}

// ---------------- tensor-core flash attention (tf32) ------------------------
// grid (S/128, H, B), 256 threads = 8 warps; warp w owns q-rows [16w,16w+16).
#define QS_OFF 0
#define KS_OFF 8704
#define VT_OFF 13056
#define PS_OFF 17408
#define CM_OFF 26112
#define SMEM_WORDS 26176

__global__ __launch_bounds__(256) void attn_tc(
    const float* __restrict__ Qb, const float* __restrict__ Kb,
    const float* __restrict__ Vb, const int* __restrict__ mask,
    float* __restrict__ Oc)
{
    extern __shared__ __align__(16) unsigned smw[];
    unsigned* Qs = smw + QS_OFF;
    unsigned* Ks = smw + KS_OFF;
    unsigned* Vt = smw + VT_OFF;
    unsigned* Ps = smw + PS_OFF;
    float*    Vn = (float*)(smw + PS_OFF);
    int*      cm = (int*)(smw + CM_OFF);

    const int it  = blockIdx.x;          // q-tile of 128 rows
    const int h   = blockIdx.y;
    const int b   = blockIdx.z;
    const int tid = threadIdx.x;
    const int w    = tid >> 5;
    const int lane = tid & 31;
    const int grp  = lane >> 2;
    const int tig  = lane & 3;

    const size_t bh = ((size_t)b * HEADS + h) * S_LEN * HD;
    const float qscale = 0.125f * 1.4426950408889634f;   // 1/sqrt(64) * log2(e)

    for (int e = tid; e < 2048; e += 256) {
        int r = e >> 4, c = (e & 15) << 2;
        float4 v = *(const float4*)(Qb + bh + (size_t)(it * 128 + r) * HD + c);
        *(uint4*)&Qs[r * 68 + c] = make_uint4(
            f2tf(v.x * qscale), f2tf(v.y * qscale),
            f2tf(v.z * qscale), f2tf(v.w * qscale));
    }

    const int qr0 = 16 * w + grp;
    const int qbase0 = qr0 * 68;
    const int qbase1 = qbase0 + 8 * 68;
    unsigned* Pw = Ps + w * 1088;

    float m0 = -1e30f, m1 = -1e30f, l0 = 0.f, l1 = 0.f;
    float o[8][4];
#pragma unroll
    for (int nt = 0; nt < 8; nt++)
#pragma unroll
        for (int r = 0; r < 4; r++) o[nt][r] = 0.f;

    const int njt = 2 * it + 2;

    for (int jt = 0; jt < njt; jt++) {
        __syncthreads();

        for (int e = tid; e < 1024; e += 256) {
            int r = e >> 4, c = (e & 15) << 2;
            float4 kv = *(const float4*)(Kb + bh + (size_t)(jt * 64 + r) * HD + c);
            *(uint4*)&Ks[r * 68 + c] = make_uint4(
                f2tf(kv.x), f2tf(kv.y), f2tf(kv.z), f2tf(kv.w));
            float4 vv = *(const float4*)(Vb + bh + (size_t)(jt * 64 + r) * HD + c);
            float* vn = &Vn[r * 65 + c];
            vn[0] = vv.x; vn[1] = vv.y; vn[2] = vv.z; vn[3] = vv.w;
        }
        if (tid < 64) cm[tid] = mask[b * S_LEN + jt * 64 + tid];
        __syncthreads();

        const int off = jt * 64 - it * 128;
        const bool band = (off >= 0);
        const bool wactive = !(off == 64 && w < 4);

        float s[8][4];
        if (wactive) {
#pragma unroll
            for (int nt = 0; nt < 8; nt++)
#pragma unroll
                for (int r = 0; r < 4; r++) s[nt][r] = 0.f;

#pragma unroll
            for (int kk = 0; kk < 8; kk++) {
                unsigned a[4];
                a[0] = Qs[qbase0 + kk * 8 + tig];
                a[1] = Qs[qbase1 + kk * 8 + tig];
                a[2] = Qs[qbase0 + kk * 8 + tig + 4];
                a[3] = Qs[qbase1 + kk * 8 + tig + 4];
#pragma unroll
                for (int nt = 0; nt < 8; nt++) {
                    unsigned bb[2];
                    bb[0] = Ks[(nt * 8 + grp) * 68 + kk * 8 + tig];
                    bb[1] = Ks[(nt * 8 + grp) * 68 + kk * 8 + tig + 4];
                    mma_tf32(s[nt], a, bb);
                }
            }
        }

        {
            int rkv  = ((w & 1) << 5) | lane;
            int dbas = (w >> 1) << 4;
#pragma unroll 8
            for (int i = 0; i < 16; i++) {
                int d = dbas + i;
                Vt[d * 68 + rkv] = f2tf(Vn[rkv * 65 + d]);
            }
        }

        if (wactive) {
            float mx0 = -1e30f, mx1 = -1e30f;
#pragma unroll
            for (int nt = 0; nt < 8; nt++) {
                int lc0 = nt * 8 + 2 * tig;
                int lc1 = lc0 + 1;
                bool c0 = cm[lc0] != 0;
                bool c1 = cm[lc1] != 0;
                bool v00 = c0 && (!band || lc0 + off <= qr0);
                bool v01 = c1 && (!band || lc1 + off <= qr0);
                bool v10 = c0 && (!band || lc0 + off <= qr0 + 8);
                bool v11 = c1 && (!band || lc1 + off <= qr0 + 8);
                s[nt][0] = v00 ? s[nt][0] : -1e30f;
                s[nt][1] = v01 ? s[nt][1] : -1e30f;
                s[nt][2] = v10 ? s[nt][2] : -1e30f;
                s[nt][3] = v11 ? s[nt][3] : -1e30f;
                mx0 = fmaxf(mx0, fmaxf(s[nt][0], s[nt][1]));
                mx1 = fmaxf(mx1, fmaxf(s[nt][2], s[nt][3]));
            }
            mx0 = fmaxf(mx0, __shfl_xor_sync(0xffffffffu, mx0, 1));
            mx0 = fmaxf(mx0, __shfl_xor_sync(0xffffffffu, mx0, 2));
            mx1 = fmaxf(mx1, __shfl_xor_sync(0xffffffffu, mx1, 1));
            mx1 = fmaxf(mx1, __shfl_xor_sync(0xffffffffu, mx1, 2));

            float mn0 = fmaxf(m0, mx0);
            float mn1 = fmaxf(m1, mx1);
            float al0 = ex2(m0 - mn0);
            float al1 = ex2(m1 - mn1);
            float ls0 = 0.f, ls1 = 0.f;
#pragma unroll
            for (int nt = 0; nt < 8; nt++) {
                s[nt][0] = ex2(s[nt][0] - mn0); ls0 += s[nt][0];
                s[nt][1] = ex2(s[nt][1] - mn0); ls0 += s[nt][1];
                s[nt][2] = ex2(s[nt][2] - mn1); ls1 += s[nt][2];
                s[nt][3] = ex2(s[nt][3] - mn1); ls1 += s[nt][3];
            }
            ls0 += __shfl_xor_sync(0xffffffffu, ls0, 1);
            ls0 += __shfl_xor_sync(0xffffffffu, ls0, 2);
            ls1 += __shfl_xor_sync(0xffffffffu, ls1, 1);
            ls1 += __shfl_xor_sync(0xffffffffu, ls1, 2);

            l0 = l0 * al0 + ls0;
            l1 = l1 * al1 + ls1;
            m0 = mn0;
            m1 = mn1;
#pragma unroll
            for (int nt = 0; nt < 8; nt++) {
                o[nt][0] *= al0; o[nt][1] *= al0;
                o[nt][2] *= al1; o[nt][3] *= al1;
            }
        }

        __syncthreads();

        if (wactive) {
#pragma unroll
            for (int nt = 0; nt < 8; nt++) {
                int cbase = nt * 8 + 2 * tig;
                Pw[grp * 68 + cbase]           = f2tf(s[nt][0]);
                Pw[grp * 68 + cbase + 1]       = f2tf(s[nt][1]);
                Pw[(grp + 8) * 68 + cbase]     = f2tf(s[nt][2]);
                Pw[(grp + 8) * 68 + cbase + 1] = f2tf(s[nt][3]);
            }
            __syncwarp();

#pragma unroll
            for (int kk = 0; kk < 8; kk++) {
                unsigned a[4];
                a[0] = Pw[grp * 68 + kk * 8 + tig];
                a[1] = Pw[(grp + 8) * 68 + kk * 8 + tig];
                a[2] = Pw[grp * 68 + kk * 8 + tig + 4];
                a[3] = Pw[(grp + 8) * 68 + kk * 8 + tig + 4];
#pragma unroll
                for (int nt = 0; nt < 8; nt++) {
                    unsigned bb[2];
                    bb[0] = Vt[(nt * 8 + grp) * 68 + kk * 8 + tig];
                    bb[1] = Vt[(nt * 8 + grp) * 68 + kk * 8 + tig + 4];
                    mma_tf32(o[nt], a, bb);
                }
            }
        }
    }

    int g0 = it * 128 + qr0;
    int g1 = g0 + 8;
    int rv0 = mask[b * S_LEN + g0];
    int rv1 = mask[b * S_LEN + g1];
    float inv0 = (rv0 != 0 && m0 > -1e29f) ? (1.f / l0) : 0.f;
    float inv1 = (rv1 != 0 && m1 > -1e29f) ? (1.f / l1) : 0.f;
    size_t ro0 = ((size_t)b * S_LEN + g0) * DM + h * 64;
    size_t ro1 = ((size_t)b * S_LEN + g1) * DM + h * 64;
#pragma unroll
    for (int nt = 0; nt < 8; nt++) {
        int cc = nt * 8 + 2 * tig;
        float2 w0 = make_float2(o[nt][0] * inv0, o[nt][1] * inv0);
        float2 w1 = make_float2(o[nt][2] * inv1, o[nt][3] * inv1);
        *(float2*)&Oc[ro0 + cc] = w0;
        *(float2*)&Oc[ro1 + cc] = w1;
    }
}

// ---------------- host ------------------------------------------------------
extern "C" void kernel_launch(void* const* d_in, const int* in_sizes, int n_in,
                              void* d_out, int out_size)
{
    const float* x    = (const float*)d_in[0];
    const int*   mask = (const int*)  d_in[1];
    const float* Wq   = (const float*)d_in[2];
    const float* bq   = (const float*)d_in[3];
    const float* Wk   = (const float*)d_in[4];
    const float* bk   = (const float*)d_in[5];
    const float* Wv   = (const float*)d_in[6];
    const float* bv   = (const float*)d_in[7];
    const float* Wo   = (const float*)d_in[8];
    const float* bo   = (const float*)d_in[9];
    float* out = (float*)d_out;

    float *qp, *kp, *vp, *cp;
    cudaGetSymbolAddress((void**)&qp, g_q);
    cudaGetSymbolAddress((void**)&kp, g_k);
    cudaGetSymbolAddress((void**)&vp, g_v);
    cudaGetSymbolAddress((void**)&cp, g_cat);

    static int attr_set = 0;
    size_t asmem = (size_t)SMEM_WORDS * 4;   // 104704 B
    if (!attr_set) {
        cudaFuncSetAttribute(attn_tc, cudaFuncAttributeMaxDynamicSharedMemorySize, (int)asmem);
        cudaFuncSetAttribute(gemm_qkv, cudaFuncAttributeMaxDynamicSharedMemorySize, GEMM_SMEM);
        cudaFuncSetAttribute(gemm_out, cudaFuncAttributeMaxDynamicSharedMemorySize, GEMM_SMEM);
        attr_set = 1;
    }

    dim3 gqkv(DM / 128, M_TOT / 128, 3);   // (8, 32, 3)
    gemm_qkv<<<gqkv, 256, GEMM_SMEM>>>(x, Wq, bq, qp, Wk, bk, kp, Wv, bv, vp);

    dim3 gattn(S_LEN / 128, HEADS, BATCH);  // (16, 16, 2)
    attn_tc<<<gattn, 256, asmem>>>(qp, kp, vp, mask, cp);

    dim3 ggemm(DM / 128, M_TOT / 128);     // (8, 32)
    gemm_out<<<ggemm, 256, GEMM_SMEM>>>(cp, Wo, bo, out);
}

// round 14
// speedup vs baseline: 1.0525x; 1.0525x over previous
#include <cuda_runtime.h>
#include <cuda_fp16.h>
#include <cstdint>
#include <math.h>

#define BATCH   2
#define S_LEN   2048
#define HEADS   16
#define HD      64
#define DM      1024
#define M_TOT   (BATCH * S_LEN)          // 4096

// ---------------- scratch (device globals: allocation-free) ----------------
__device__ float g_q[BATCH * HEADS * S_LEN * HD];    // [B,H,S,64]
__device__ float g_k[BATCH * HEADS * S_LEN * HD];
__device__ float g_v[BATCH * HEADS * S_LEN * HD];
__device__ float g_cat[BATCH * S_LEN * DM];          // [B,S,H*64]

// ---------------- helpers ---------------------------------------------------
__device__ __forceinline__ unsigned f2h2(float x, float y) {
    __half2 h = __floats2half2_rn(x, y);   // low = x, high = y
    return *reinterpret_cast<unsigned*>(&h);
}

__device__ __forceinline__ void mma_fp16(float* c, const unsigned* a, const unsigned* b) {
    asm volatile(
        "mma.sync.aligned.m16n8k16.row.col.f32.f16.f16.f32 "
        "{%0,%1,%2,%3}, {%4,%5,%6,%7}, {%8,%9}, {%0,%1,%2,%3};\n"
        : "+f"(c[0]), "+f"(c[1]), "+f"(c[2]), "+f"(c[3])
        : "r"(a[0]), "r"(a[1]), "r"(a[2]), "r"(a[3]), "r"(b[0]), "r"(b[1]));
}

__device__ __forceinline__ float ex2(float x) {
    float r;
    asm("ex2.approx.f32 %0, %1;" : "=f"(r) : "f"(x));
    return r;
}

// ---------------- fp16 tensor-core GEMM (m16n8k16, double-buffered) --------
// C[M,N] = A[M,K] * W[N,K]^T + bias; CTA 128x128, BK=64 halfs (32 words),
// 16 chunks, 8 warps (2x4), warp tile 64x32.
#define LDW 36                       // word (half2) stride per row
#define BUF_W (128 * LDW)            // 4608 words per operand buffer
#define GEMM_SMEM (4 * BUF_W * 4)    // A0,W0,A1,W1 = 73728 bytes
#define NCHUNK 16

__device__ __forceinline__ void gemm_body(
    const float* __restrict__ A, const float* __restrict__ W,
    const float* __restrict__ bias, float* __restrict__ C, int scatter)
{
    extern __shared__ __align__(16) unsigned gsm[];
    unsigned* Abuf[2] = { gsm,            gsm + 2 * BUF_W };
    unsigned* Wbuf[2] = { gsm + BUF_W,    gsm + 3 * BUF_W };

    const int tid  = threadIdx.x;
    const int lane = tid & 31;
    const int wid  = tid >> 5;
    const int wm   = wid >> 2;        // m offset wm*64
    const int wn   = wid & 3;         // n offset wn*32
    const int bm   = blockIdx.y * 128;
    const int bn   = blockIdx.x * 128;

    const int grp = lane >> 2;
    const int tig = lane & 3;

    const int lrow = tid >> 1;             // 0..127
    const int half = tid & 1;              // which 32-float half of the row
    const int idx4 = lrow * 9 + half * 4;  // uint4 index (36 words = 9 uint4/row)

    const float* Ap = A + (size_t)(bm + lrow) * DM + half * 32;
    const float* Wp = W + (size_t)(bn + lrow) * DM + half * 32;

    float c[4][4][4];
#pragma unroll
    for (int i = 0; i < 4; i++)
#pragma unroll
        for (int j = 0; j < 4; j++)
#pragma unroll
            for (int r = 0; r < 4; r++) c[i][j][r] = 0.f;

    unsigned pa[16], pw[16];
    // prefetch + stage chunk 0 into buffer 0
#pragma unroll
    for (int u = 0; u < 8; u++) {
        float4 va = *(const float4*)(Ap + 4 * u);
        pa[2 * u]     = f2h2(va.x, va.y);
        pa[2 * u + 1] = f2h2(va.z, va.w);
        float4 vw = *(const float4*)(Wp + 4 * u);
        pw[2 * u]     = f2h2(vw.x, vw.y);
        pw[2 * u + 1] = f2h2(vw.z, vw.w);
    }
    {
        uint4* a4 = (uint4*)Abuf[0] + idx4;
        uint4* w4 = (uint4*)Wbuf[0] + idx4;
#pragma unroll
        for (int u = 0; u < 4; u++) {
            a4[u] = make_uint4(pa[4 * u], pa[4 * u + 1], pa[4 * u + 2], pa[4 * u + 3]);
            w4[u] = make_uint4(pw[4 * u], pw[4 * u + 1], pw[4 * u + 2], pw[4 * u + 3]);
        }
    }
    __syncthreads();

    for (int kt = 0; kt < NCHUNK; kt++) {
        const int cur = kt & 1;
        const unsigned* As = Abuf[cur];
        const unsigned* Ws = Wbuf[cur];

        // prefetch next chunk (64 floats per thread -> 32 half2 words)
        if (kt + 1 < NCHUNK) {
#pragma unroll
            for (int u = 0; u < 8; u++) {
                float4 va = *(const float4*)(Ap + (kt + 1) * 64 + 4 * u);
                pa[2 * u]     = f2h2(va.x, va.y);
                pa[2 * u + 1] = f2h2(va.z, va.w);
                float4 vw = *(const float4*)(Wp + (kt + 1) * 64 + 4 * u);
                pw[2 * u]     = f2h2(vw.x, vw.y);
                pw[2 * u + 1] = f2h2(vw.z, vw.w);
            }
        }

        // 4 k16 steps per chunk (8 words each)
#pragma unroll
        for (int ks = 0; ks < 4; ks++) {
            unsigned b[4][2];
#pragma unroll
            for (int j = 0; j < 4; j++) {
                int n = wn * 32 + j * 8 + grp;
                int k = ks * 8 + tig;
                b[j][0] = Ws[n * LDW + k];
                b[j][1] = Ws[n * LDW + k + 4];
            }
#pragma unroll
            for (int i = 0; i < 4; i++) {
                unsigned a[4];
                int m = wm * 64 + i * 16 + grp;
                int k = ks * 8 + tig;
                a[0] = As[m * LDW + k];
                a[1] = As[(m + 8) * LDW + k];
                a[2] = As[m * LDW + k + 4];
                a[3] = As[(m + 8) * LDW + k + 4];
#pragma unroll
                for (int j = 0; j < 4; j++)
                    mma_fp16(c[i][j], a, b[j]);
            }
        }

        if (kt + 1 < NCHUNK) {
            uint4* a4 = (uint4*)Abuf[cur ^ 1] + idx4;
            uint4* w4 = (uint4*)Wbuf[cur ^ 1] + idx4;
#pragma unroll
            for (int u = 0; u < 4; u++) {
                a4[u] = make_uint4(pa[4 * u], pa[4 * u + 1], pa[4 * u + 2], pa[4 * u + 3]);
                w4[u] = make_uint4(pw[4 * u], pw[4 * u + 1], pw[4 * u + 2], pw[4 * u + 3]);
            }
        }
        __syncthreads();
    }

    // epilogue: bias + store
#pragma unroll
    for (int j = 0; j < 4; j++) {
        int n0 = bn + wn * 32 + j * 8 + 2 * tig;
        float bia0 = bias[n0];
        float bia1 = bias[n0 + 1];
#pragma unroll
        for (int i = 0; i < 4; i++) {
            int m0 = bm + wm * 64 + i * 16 + grp;
            float2 v0 = make_float2(c[i][j][0] + bia0, c[i][j][1] + bia1);
            float2 v1 = make_float2(c[i][j][2] + bia0, c[i][j][3] + bia1);
            if (scatter) {
                int h = n0 >> 6, d = n0 & 63;
                int b0 = m0 >> 11, s0 = m0 & 2047;
                int b1 = (m0 + 8) >> 11, s1 = (m0 + 8) & 2047;
                *(float2*)&C[(((size_t)b0 * HEADS + h) * S_LEN + s0) * HD + d] = v0;
                *(float2*)&C[(((size_t)b1 * HEADS + h) * S_LEN + s1) * HD + d] = v1;
            } else {
                *(float2*)&C[(size_t)m0 * DM + n0] = v0;
                *(float2*)&C[(size_t)(m0 + 8) * DM + n0] = v1;
            }
        }
    }
}

__global__ __launch_bounds__(256) void gemm_qkv(
    const float* __restrict__ x,
    const float* __restrict__ Wq, const float* __restrict__ bq, float* __restrict__ Oq,
    const float* __restrict__ Wk, const float* __restrict__ bk, float* __restrict__ Ok,
    const float* __restrict__ Wv, const float* __restrict__ bv, float* __restrict__ Ov)
{
    int z = blockIdx.z;
    const float* W = (z == 0) ? Wq : (z == 1) ? Wk : Wv;
    const float* bb = (z == 0) ? bq : (z == 1) ? bk : bv;
    float* O = (z == 0) ? Oq : (z == 1) ? Ok : Ov;
    gemm_body(x, W, bb, O, 1);
}

__global__ __launch_bounds__(256) void gemm_out(
    const float* __restrict__ A, const float* __restrict__ W,
    const float* __restrict__ bias, float* __restrict__ C)
{
    gemm_body(A, W, bias, C, 0);
}

// ---------------- fp16 tensor-core flash attention --------------------------
// grid (S/128, H, B), 256 threads = 8 warps; warp w owns q-rows [16w,16w+16).
// smem (words = half2 unless noted):
//   Qs [128*36]  fp16 Q (pre-scaled by 0.125*log2e)     @0
//   Ks [64*36]   fp16 K (kv-major)                      @4608
//   Vt [64*36]   fp16 V^T (d-major)                     @6912
//   Ps [8*16*36] per-warp P staging (aliases Vn fp32 [64*65]) @9216
//   cm [64] int                                         @13824
#define QS_OFF 0
#define KS_OFF 4608
#define VT_OFF 6912
#define PS_OFF 9216
#define CM_OFF 13824
#define ASMEM_WORDS 13888

__global__ __launch_bounds__(256) void attn_tc(
    const float* __restrict__ Qb, const float* __restrict__ Kb,
    const float* __restrict__ Vb, const int* __restrict__ mask,
    float* __restrict__ Oc)
{
    extern __shared__ __align__(16) unsigned smw[];
    unsigned* Qs = smw + QS_OFF;
    unsigned* Ks = smw + KS_OFF;
    unsigned* Vt = smw + VT_OFF;
    unsigned* Ps = smw + PS_OFF;
    float*    Vn = (float*)(smw + PS_OFF);
    int*      cm = (int*)(smw + CM_OFF);

    const int it  = blockIdx.x;          // q-tile of 128 rows
    const int h   = blockIdx.y;
    const int b   = blockIdx.z;
    const int tid = threadIdx.x;
    const int w    = tid >> 5;
    const int lane = tid & 31;
    const int grp  = lane >> 2;
    const int tig  = lane & 3;

    const size_t bh = ((size_t)b * HEADS + h) * S_LEN * HD;
    const float qscale = 0.125f * 1.4426950408889634f;   // 1/sqrt(64) * log2(e)

    // ---- load Q tile: 128 rows x 32 words ----
    for (int e = tid; e < 1024; e += 256) {
        int r = e >> 3, wc = (e & 7) << 2;           // word col base
        const float* src = Qb + bh + (size_t)(it * 128 + r) * HD + 2 * wc;
        float4 f0 = *(const float4*)(src);
        float4 f1 = *(const float4*)(src + 4);
        *(uint4*)&Qs[r * 36 + wc] = make_uint4(
            f2h2(f0.x * qscale, f0.y * qscale), f2h2(f0.z * qscale, f0.w * qscale),
            f2h2(f1.x * qscale, f1.y * qscale), f2h2(f1.z * qscale, f1.w * qscale));
    }

    const int qr0 = 16 * w + grp;
    const int qbase0 = qr0 * 36;
    const int qbase1 = qbase0 + 8 * 36;
    unsigned* Pw = Ps + w * 576;                     // 16 x 36 words per warp

    float m0 = -1e30f, m1 = -1e30f, l0 = 0.f, l1 = 0.f;
    float o[8][4];
#pragma unroll
    for (int nt = 0; nt < 8; nt++)
#pragma unroll
        for (int r = 0; r < 4; r++) o[nt][r] = 0.f;

    const int njt = 2 * it + 2;

    for (int jt = 0; jt < njt; jt++) {
        __syncthreads();   // prior iter's readers of Ks/Vt/Ps done

        // ---- K -> Ks (fp16 words), V -> Vn (fp32 scratch) ----
        for (int e = tid; e < 512; e += 256) {
            int r = e >> 3, wc = (e & 7) << 2;
            const float* src = Kb + bh + (size_t)(jt * 64 + r) * HD + 2 * wc;
            float4 f0 = *(const float4*)(src);
            float4 f1 = *(const float4*)(src + 4);
            *(uint4*)&Ks[r * 36 + wc] = make_uint4(
                f2h2(f0.x, f0.y), f2h2(f0.z, f0.w),
                f2h2(f1.x, f1.y), f2h2(f1.z, f1.w));
        }
        for (int e = tid; e < 1024; e += 256) {
            int r = e >> 4, c = (e & 15) << 2;
            float4 vv = *(const float4*)(Vb + bh + (size_t)(jt * 64 + r) * HD + c);
            float* vn = &Vn[r * 65 + c];
            vn[0] = vv.x; vn[1] = vv.y; vn[2] = vv.z; vn[3] = vv.w;
        }
        if (tid < 64) cm[tid] = mask[b * S_LEN + jt * 64 + tid];
        __syncthreads();   // Ks/Vn/cm ready

        const int off = jt * 64 - it * 128;
        const bool band = (off >= 0);
        const bool wactive = !(off == 64 && w < 4);

        float s[8][4];
        if (wactive) {
#pragma unroll
            for (int nt = 0; nt < 8; nt++)
#pragma unroll
                for (int r = 0; r < 4; r++) s[nt][r] = 0.f;

#pragma unroll
            for (int ks = 0; ks < 4; ks++) {
                unsigned a[4];
                int k = ks * 8 + tig;
                a[0] = Qs[qbase0 + k];
                a[1] = Qs[qbase1 + k];
                a[2] = Qs[qbase0 + k + 4];
                a[3] = Qs[qbase1 + k + 4];
#pragma unroll
                for (int nt = 0; nt < 8; nt++) {
                    unsigned bb[2];
                    bb[0] = Ks[(nt * 8 + grp) * 36 + k];
                    bb[1] = Ks[(nt * 8 + grp) * 36 + k + 4];
                    mma_fp16(s[nt], a, bb);
                }
            }
        }

        // ---- build Vt (d-major fp16 words) from Vn ----
        {
            int d  = tid >> 2;                 // 0..63
            int kb = (tid & 3) << 3;           // kv-pair base
#pragma unroll
            for (int i = 0; i < 8; i++) {
                int kp = kb + i;
                Vt[d * 36 + kp] = f2h2(Vn[(2 * kp) * 65 + d], Vn[(2 * kp + 1) * 65 + d]);
            }
        }

        if (wactive) {
            // ---- mask + online softmax (fp32 registers) ----
            float mx0 = -1e30f, mx1 = -1e30f;
#pragma unroll
            for (int nt = 0; nt < 8; nt++) {
                int lc0 = nt * 8 + 2 * tig;
                int lc1 = lc0 + 1;
                bool c0 = cm[lc0] != 0;
                bool c1 = cm[lc1] != 0;
                bool v00 = c0 && (!band || lc0 + off <= qr0);
                bool v01 = c1 && (!band || lc1 + off <= qr0);
                bool v10 = c0 && (!band || lc0 + off <= qr0 + 8);
                bool v11 = c1 && (!band || lc1 + off <= qr0 + 8);
                s[nt][0] = v00 ? s[nt][0] : -1e30f;
                s[nt][1] = v01 ? s[nt][1] : -1e30f;
                s[nt][2] = v10 ? s[nt][2] : -1e30f;
                s[nt][3] = v11 ? s[nt][3] : -1e30f;
                mx0 = fmaxf(mx0, fmaxf(s[nt][0], s[nt][1]));
                mx1 = fmaxf(mx1, fmaxf(s[nt][2], s[nt][3]));
            }
            mx0 = fmaxf(mx0, __shfl_xor_sync(0xffffffffu, mx0, 1));
            mx0 = fmaxf(mx0, __shfl_xor_sync(0xffffffffu, mx0, 2));
            mx1 = fmaxf(mx1, __shfl_xor_sync(0xffffffffu, mx1, 1));
            mx1 = fmaxf(mx1, __shfl_xor_sync(0xffffffffu, mx1, 2));

            float mn0 = fmaxf(m0, mx0);
            float mn1 = fmaxf(m1, mx1);
            float al0 = ex2(m0 - mn0);
            float al1 = ex2(m1 - mn1);
            float ls0 = 0.f, ls1 = 0.f;
#pragma unroll
            for (int nt = 0; nt < 8; nt++) {
                s[nt][0] = ex2(s[nt][0] - mn0); ls0 += s[nt][0];
                s[nt][1] = ex2(s[nt][1] - mn0); ls0 += s[nt][1];
                s[nt][2] = ex2(s[nt][2] - mn1); ls1 += s[nt][2];
                s[nt][3] = ex2(s[nt][3] - mn1); ls1 += s[nt][3];
            }
            ls0 += __shfl_xor_sync(0xffffffffu, ls0, 1);
            ls0 += __shfl_xor_sync(0xffffffffu, ls0, 2);
            ls1 += __shfl_xor_sync(0xffffffffu, ls1, 1);
            ls1 += __shfl_xor_sync(0xffffffffu, ls1, 2);

            l0 = l0 * al0 + ls0;
            l1 = l1 * al1 + ls1;
            m0 = mn0;
            m1 = mn1;
#pragma unroll
            for (int nt = 0; nt < 8; nt++) {
                o[nt][0] *= al0; o[nt][1] *= al0;
                o[nt][2] *= al1; o[nt][3] *= al1;
            }
        }

        __syncthreads();   // Vt complete everywhere; Vn readers done (Ps may alias-write)

        if (wactive) {
            // ---- stage P (fp16 words) per warp; C-frag -> A-frag reshape ----
#pragma unroll
            for (int nt = 0; nt < 8; nt++) {
                int wc = nt * 4 + tig;
                Pw[grp * 36 + wc]       = f2h2(s[nt][0], s[nt][1]);
                Pw[(grp + 8) * 36 + wc] = f2h2(s[nt][2], s[nt][3]);
            }
            __syncwarp();

            // ---- O += P V ----
#pragma unroll
            for (int ks = 0; ks < 4; ks++) {
                unsigned a[4];
                int k = ks * 8 + tig;
                a[0] = Pw[grp * 36 + k];
                a[1] = Pw[(grp + 8) * 36 + k];
                a[2] = Pw[grp * 36 + k + 4];
                a[3] = Pw[(grp + 8) * 36 + k + 4];
#pragma unroll
                for (int nt = 0; nt < 8; nt++) {
                    unsigned bb[2];
                    bb[0] = Vt[(nt * 8 + grp) * 36 + k];
                    bb[1] = Vt[(nt * 8 + grp) * 36 + k + 4];
                    mma_fp16(o[nt], a, bb);
                }
            }
        }
    }

    // ---- epilogue: normalize, write concat [B,S,H*64] ----
    int g0 = it * 128 + qr0;
    int g1 = g0 + 8;
    int rv0 = mask[b * S_LEN + g0];
    int rv1 = mask[b * S_LEN + g1];
    float inv0 = (rv0 != 0 && m0 > -1e29f) ? (1.f / l0) : 0.f;
    float inv1 = (rv1 != 0 && m1 > -1e29f) ? (1.f / l1) : 0.f;
    size_t ro0 = ((size_t)b * S_LEN + g0) * DM + h * 64;
    size_t ro1 = ((size_t)b * S_LEN + g1) * DM + h * 64;
#pragma unroll
    for (int nt = 0; nt < 8; nt++) {
        int cc = nt * 8 + 2 * tig;
        float2 w0 = make_float2(o[nt][0] * inv0, o[nt][1] * inv0);
        float2 w1 = make_float2(o[nt][2] * inv1, o[nt][3] * inv1);
        *(float2*)&Oc[ro0 + cc] = w0;
        *(float2*)&Oc[ro1 + cc] = w1;
    }
}

// ---------------- host ------------------------------------------------------
extern "C" void kernel_launch(void* const* d_in, const int* in_sizes, int n_in,
                              void* d_out, int out_size)
{
    const float* x    = (const float*)d_in[0];
    const int*   mask = (const int*)  d_in[1];
    const float* Wq   = (const float*)d_in[2];
    const float* bq   = (const float*)d_in[3];
    const float* Wk   = (const float*)d_in[4];
    const float* bk   = (const float*)d_in[5];
    const float* Wv   = (const float*)d_in[6];
    const float* bv   = (const float*)d_in[7];
    const float* Wo   = (const float*)d_in[8];
    const float* bo   = (const float*)d_in[9];
    float* out = (float*)d_out;

    float *qp, *kp, *vp, *cp;
    cudaGetSymbolAddress((void**)&qp, g_q);
    cudaGetSymbolAddress((void**)&kp, g_k);
    cudaGetSymbolAddress((void**)&vp, g_v);
    cudaGetSymbolAddress((void**)&cp, g_cat);

    static int attr_set = 0;
    size_t asmem = (size_t)ASMEM_WORDS * 4;   // 55552 B
    if (!attr_set) {
        cudaFuncSetAttribute(attn_tc, cudaFuncAttributeMaxDynamicSharedMemorySize, (int)asmem);
        cudaFuncSetAttribute(gemm_qkv, cudaFuncAttributeMaxDynamicSharedMemorySize, GEMM_SMEM);
        cudaFuncSetAttribute(gemm_out, cudaFuncAttributeMaxDynamicSharedMemorySize, GEMM_SMEM);
        attr_set = 1;
    }

    dim3 gqkv(DM / 128, M_TOT / 128, 3);   // (8, 32, 3)
    gemm_qkv<<<gqkv, 256, GEMM_SMEM>>>(x, Wq, bq, qp, Wk, bk, kp, Wv, bv, vp);

    dim3 gattn(S_LEN / 128, HEADS, BATCH);  // (16, 16, 2)
    attn_tc<<<gattn, 256, asmem>>>(qp, kp, vp, mask, cp);

    dim3 ggemm(DM / 128, M_TOT / 128);     // (8, 32)
    gemm_out<<<ggemm, 256, GEMM_SMEM>>>(cp, Wo, bo, out);
}

// round 16
// speedup vs baseline: 1.8219x; 1.7310x over previous
#include <cuda_runtime.h>
#include <cuda_fp16.h>
#include <cstdint>
#include <math.h>

#define BATCH   2
#define S_LEN   2048
#define HEADS   16
#define HD      64
#define DM      1024
#define M_TOT   (BATCH * S_LEN)          // 4096

// ---------------- scratch (device globals: allocation-free) ----------------
__device__ float  g_q[BATCH * HEADS * S_LEN * HD];   // [B,H,S,64] fp32
__device__ float  g_k[BATCH * HEADS * S_LEN * HD];
__device__ float  g_v[BATCH * HEADS * S_LEN * HD];
__device__ __half g_xh [M_TOT * DM];                 // fp16 copies of inputs
__device__ __half g_wqh[DM * DM];
__device__ __half g_wkh[DM * DM];
__device__ __half g_wvh[DM * DM];
__device__ __half g_woh[DM * DM];
__device__ __half g_cath[M_TOT * DM];                // attn output concat (fp16)

// ---------------- helpers ---------------------------------------------------
__device__ __forceinline__ unsigned f2h2(float x, float y) {
    __half2 h = __floats2half2_rn(x, y);   // low = x, high = y
    return *reinterpret_cast<unsigned*>(&h);
}

__device__ __forceinline__ void mma_fp16(float* c, const unsigned* a, const unsigned* b) {
    asm volatile(
        "mma.sync.aligned.m16n8k16.row.col.f32.f16.f16.f32 "
        "{%0,%1,%2,%3}, {%4,%5,%6,%7}, {%8,%9}, {%0,%1,%2,%3};\n"
        : "+f"(c[0]), "+f"(c[1]), "+f"(c[2]), "+f"(c[3])
        : "r"(a[0]), "r"(a[1]), "r"(a[2]), "r"(a[3]), "r"(b[0]), "r"(b[1]));
}

__device__ __forceinline__ float ex2(float x) {
    float r;
    asm("ex2.approx.f32 %0, %1;" : "=f"(r) : "f"(x));
    return r;
}

__device__ __forceinline__ void cp16(uint32_t dst, const void* src) {
    asm volatile("cp.async.cg.shared.global [%0], [%1], 16;" :: "r"(dst), "l"(src));
}
__device__ __forceinline__ void cp_commit() {
    asm volatile("cp.async.commit_group;" ::: "memory");
}
template <int N>
__device__ __forceinline__ void cp_wait() {
    asm volatile("cp.async.wait_group %0;" :: "n"(N) : "memory");
}

// ---------------- fp16 pre-convert ------------------------------------------
__global__ __launch_bounds__(256) void cvt_all(
    const float* __restrict__ x,
    const float* __restrict__ wq, const float* __restrict__ wk,
    const float* __restrict__ wv, const float* __restrict__ wo)
{
    int i = blockIdx.x * 256 + threadIdx.x;       // float4 index, 0..1048575
    float4 v = *(const float4*)(x + 4 * (size_t)i);
    *(uint2*)((__half*)g_xh + 4 * (size_t)i) =
        make_uint2(f2h2(v.x, v.y), f2h2(v.z, v.w));
    if (i < 262144) {
        float4 a = *(const float4*)(wq + 4 * (size_t)i);
        *(uint2*)((__half*)g_wqh + 4 * (size_t)i) = make_uint2(f2h2(a.x, a.y), f2h2(a.z, a.w));
        float4 b = *(const float4*)(wk + 4 * (size_t)i);
        *(uint2*)((__half*)g_wkh + 4 * (size_t)i) = make_uint2(f2h2(b.x, b.y), f2h2(b.z, b.w));
        float4 c = *(const float4*)(wv + 4 * (size_t)i);
        *(uint2*)((__half*)g_wvh + 4 * (size_t)i) = make_uint2(f2h2(c.x, c.y), f2h2(c.z, c.w));
        float4 d = *(const float4*)(wo + 4 * (size_t)i);
        *(uint2*)((__half*)g_woh + 4 * (size_t)i) = make_uint2(f2h2(d.x, d.y), f2h2(d.z, d.w));
    }
}

// ---------------- fp16 GEMM with cp.async pipeline ---------------------------
// C[M,N] = A[M,K]*W[N,K]^T + bias; A,W fp16 in gmem; CTA 128x128, BK=64 halfs,
// 16 chunks, 3-stage cp.async pipeline, 8 warps (2x4), warp tile 64x32.
#define LDW 36                          // half2-words per smem row (32 data + 4 pad)
#define TILEB (128 * LDW * 4)           // bytes per operand tile buffer (18432)
#define STAGES 3
#define GEMM_SMEM (STAGES * 2 * TILEB)  // 110592 bytes
#define NCHUNK 16

__device__ __forceinline__ void gemm_issue_chunk(
    uint32_t sb, int stage, int kt,
    const __half* __restrict__ A, const __half* __restrict__ W,
    int bm, int bn, int tid)
{
    uint32_t abase = sb + stage * 2 * TILEB;
    uint32_t wbase = abase + TILEB;
#pragma unroll
    for (int u = 0; u < 4; u++) {
        int seg = tid + 256 * u;          // 0..1023
        int row = seg >> 3;               // 0..127
        int sc  = seg & 7;                // 16B segment in row
        uint32_t doff = (uint32_t)(row * LDW + sc * 4) * 4;
        cp16(abase + doff, A + (size_t)(bm + row) * DM + kt * 64 + sc * 8);
        cp16(wbase + doff, W + (size_t)(bn + row) * DM + kt * 64 + sc * 8);
    }
}

__device__ __forceinline__ void gemm_body(
    const __half* __restrict__ A, const __half* __restrict__ W,
    const float* __restrict__ bias, float* __restrict__ C, int scatter)
{
    extern __shared__ __align__(16) char gsm[];
    uint32_t sb = (uint32_t)__cvta_generic_to_shared(gsm);

    const int tid  = threadIdx.x;
    const int lane = tid & 31;
    const int wid  = tid >> 5;
    const int wm   = wid >> 2;
    const int wn   = wid & 3;
    const int bm   = blockIdx.y * 128;
    const int bn   = blockIdx.x * 128;
    const int grp  = lane >> 2;
    const int tig  = lane & 3;

    float c[4][4][4];
#pragma unroll
    for (int i = 0; i < 4; i++)
#pragma unroll
        for (int j = 0; j < 4; j++)
#pragma unroll
            for (int r = 0; r < 4; r++) c[i][j][r] = 0.f;

    // prologue: issue STAGES-1 chunks
#pragma unroll
    for (int s = 0; s < STAGES - 1; s++) {
        gemm_issue_chunk(sb, s, s, A, W, bm, bn, tid);
        cp_commit();
    }

    for (int kt = 0; kt < NCHUNK; kt++) {
        cp_wait<STAGES - 2>();            // chunk kt arrived
        __syncthreads();                  // visible to all; prior mma on reused buf done

        // issue chunk kt+STAGES-1 into its buffer
        if (kt + STAGES - 1 < NCHUNK)
            gemm_issue_chunk(sb, (kt + STAGES - 1) % STAGES, kt + STAGES - 1, A, W, bm, bn, tid);
        cp_commit();                      // always commit (may be empty group)

        const unsigned* As = (const unsigned*)(gsm + (kt % STAGES) * 2 * TILEB);
        const unsigned* Ws = (const unsigned*)(gsm + (kt % STAGES) * 2 * TILEB + TILEB);

#pragma unroll
        for (int ks = 0; ks < 4; ks++) {
            unsigned b[4][2];
#pragma unroll
            for (int j = 0; j < 4; j++) {
                int n = wn * 32 + j * 8 + grp;
                int k = ks * 8 + tig;
                b[j][0] = Ws[n * LDW + k];
                b[j][1] = Ws[n * LDW + k + 4];
            }
#pragma unroll
            for (int i = 0; i < 4; i++) {
                unsigned a[4];
                int m = wm * 64 + i * 16 + grp;
                int k = ks * 8 + tig;
                a[0] = As[m * LDW + k];
                a[1] = As[(m + 8) * LDW + k];
                a[2] = As[m * LDW + k + 4];
                a[3] = As[(m + 8) * LDW + k + 4];
#pragma unroll
                for (int j = 0; j < 4; j++)
                    mma_fp16(c[i][j], a, b[j]);
            }
        }
        __syncthreads();                  // all warps done with buf kt%STAGES
    }

    // epilogue: bias + store fp32
#pragma unroll
    for (int j = 0; j < 4; j++) {
        int n0 = bn + wn * 32 + j * 8 + 2 * tig;
        float bia0 = bias[n0];
        float bia1 = bias[n0 + 1];
#pragma unroll
        for (int i = 0; i < 4; i++) {
            int m0 = bm + wm * 64 + i * 16 + grp;
            float2 v0 = make_float2(c[i][j][0] + bia0, c[i][j][1] + bia1);
            float2 v1 = make_float2(c[i][j][2] + bia0, c[i][j][3] + bia1);
            if (scatter) {
                int h = n0 >> 6, d = n0 & 63;
                int b0 = m0 >> 11, s0 = m0 & 2047;
                int b1 = (m0 + 8) >> 11, s1 = (m0 + 8) & 2047;
                *(float2*)&C[(((size_t)b0 * HEADS + h) * S_LEN + s0) * HD + d] = v0;
                *(float2*)&C[(((size_t)b1 * HEADS + h) * S_LEN + s1) * HD + d] = v1;
            } else {
                *(float2*)&C[(size_t)m0 * DM + n0] = v0;
                *(float2*)&C[(size_t)(m0 + 8) * DM + n0] = v1;
            }
        }
    }
}

__global__ __launch_bounds__(256) void gemm_qkv(
    const float* __restrict__ bq, float* __restrict__ Oq,
    const float* __restrict__ bk, float* __restrict__ Ok,
    const float* __restrict__ bv, float* __restrict__ Ov)
{
    int z = blockIdx.z;
    const __half* W = (z == 0) ? (const __half*)g_wqh : (z == 1) ? (const __half*)g_wkh
                                                                 : (const __half*)g_wvh;
    const float* bb = (z == 0) ? bq : (z == 1) ? bk : bv;
    float* O = (z == 0) ? Oq : (z == 1) ? Ok : Ov;
    gemm_body((const __half*)g_xh, W, bb, O, 1);
}

__global__ __launch_bounds__(256) void gemm_out(
    const float* __restrict__ bias, float* __restrict__ C)
{
    gemm_body((const __half*)g_cath, (const __half*)g_woh, bias, C, 0);
}

// ---------------- fp16 tensor-core flash attention --------------------------
// grid (S/128, H, B), 256 threads = 8 warps; warp w owns q-rows [16w,16w+16).
#define QS_OFF 0
#define KS_OFF 4608
#define VT_OFF 6912
#define PS_OFF 9216
#define CM_OFF 13824
#define ASMEM_WORDS 13888

__global__ __launch_bounds__(256) void attn_tc(
    const float* __restrict__ Qb, const float* __restrict__ Kb,
    const float* __restrict__ Vb, const int* __restrict__ mask,
    __half* __restrict__ Oc)
{
    extern __shared__ __align__(16) unsigned smw[];
    unsigned* Qs = smw + QS_OFF;
    unsigned* Ks = smw + KS_OFF;
    unsigned* Vt = smw + VT_OFF;
    unsigned* Ps = smw + PS_OFF;
    float*    Vn = (float*)(smw + PS_OFF);
    int*      cm = (int*)(smw + CM_OFF);

    const int it  = blockIdx.x;
    const int h   = blockIdx.y;
    const int b   = blockIdx.z;
    const int tid = threadIdx.x;
    const int w    = tid >> 5;
    const int lane = tid & 31;
    const int grp  = lane >> 2;
    const int tig  = lane & 3;

    const size_t bh = ((size_t)b * HEADS + h) * S_LEN * HD;
    const float qscale = 0.125f * 1.4426950408889634f;

    for (int e = tid; e < 1024; e += 256) {
        int r = e >> 3, wc = (e & 7) << 2;
        const float* src = Qb + bh + (size_t)(it * 128 + r) * HD + 2 * wc;
        float4 f0 = *(const float4*)(src);
        float4 f1 = *(const float4*)(src + 4);
        *(uint4*)&Qs[r * 36 + wc] = make_uint4(
            f2h2(f0.x * qscale, f0.y * qscale), f2h2(f0.z * qscale, f0.w * qscale),
            f2h2(f1.x * qscale, f1.y * qscale), f2h2(f1.z * qscale, f1.w * qscale));
    }

    const int qr0 = 16 * w + grp;
    const int qbase0 = qr0 * 36;
    const int qbase1 = qbase0 + 8 * 36;
    unsigned* Pw = Ps + w * 576;

    float m0 = -1e30f, m1 = -1e30f, l0 = 0.f, l1 = 0.f;
    float o[8][4];
#pragma unroll
    for (int nt = 0; nt < 8; nt++)
#pragma unroll
        for (int r = 0; r < 4; r++) o[nt][r] = 0.f;

    const int njt = 2 * it + 2;

    for (int jt = 0; jt < njt; jt++) {
        __syncthreads();

        for (int e = tid; e < 512; e += 256) {
            int r = e >> 3, wc = (e & 7) << 2;
            const float* src = Kb + bh + (size_t)(jt * 64 + r) * HD + 2 * wc;
            float4 f0 = *(const float4*)(src);
            float4 f1 = *(const float4*)(src + 4);
            *(uint4*)&Ks[r * 36 + wc] = make_uint4(
                f2h2(f0.x, f0.y), f2h2(f0.z, f0.w),
                f2h2(f1.x, f1.y), f2h2(f1.z, f1.w));
        }
        for (int e = tid; e < 1024; e += 256) {
            int r = e >> 4, c = (e & 15) << 2;
            float4 vv = *(const float4*)(Vb + bh + (size_t)(jt * 64 + r) * HD + c);
            float* vn = &Vn[r * 65 + c];
            vn[0] = vv.x; vn[1] = vv.y; vn[2] = vv.z; vn[3] = vv.w;
        }
        if (tid < 64) cm[tid] = mask[b * S_LEN + jt * 64 + tid];
        __syncthreads();

        const int off = jt * 64 - it * 128;
        const bool band = (off >= 0);
        const bool wactive = !(off == 64 && w < 4);

        float s[8][4];
        if (wactive) {
#pragma unroll
            for (int nt = 0; nt < 8; nt++)
#pragma unroll
                for (int r = 0; r < 4; r++) s[nt][r] = 0.f;

#pragma unroll
            for (int ks = 0; ks < 4; ks++) {
                unsigned a[4];
                int k = ks * 8 + tig;
                a[0] = Qs[qbase0 + k];
                a[1] = Qs[qbase1 + k];
                a[2] = Qs[qbase0 + k + 4];
                a[3] = Qs[qbase1 + k + 4];
#pragma unroll
                for (int nt = 0; nt < 8; nt++) {
                    unsigned bb[2];
                    bb[0] = Ks[(nt * 8 + grp) * 36 + k];
                    bb[1] = Ks[(nt * 8 + grp) * 36 + k + 4];
                    mma_fp16(s[nt], a, bb);
                }
            }
        }

        {
            int d  = tid >> 2;
            int kb = (tid & 3) << 3;
#pragma unroll
            for (int i = 0; i < 8; i++) {
                int kp = kb + i;
                Vt[d * 36 + kp] = f2h2(Vn[(2 * kp) * 65 + d], Vn[(2 * kp + 1) * 65 + d]);
            }
        }

        if (wactive) {
            float mx0 = -1e30f, mx1 = -1e30f;
#pragma unroll
            for (int nt = 0; nt < 8; nt++) {
                int lc0 = nt * 8 + 2 * tig;
                int lc1 = lc0 + 1;
                bool c0 = cm[lc0] != 0;
                bool c1 = cm[lc1] != 0;
                bool v00 = c0 && (!band || lc0 + off <= qr0);
                bool v01 = c1 && (!band || lc1 + off <= qr0);
                bool v10 = c0 && (!band || lc0 + off <= qr0 + 8);
                bool v11 = c1 && (!band || lc1 + off <= qr0 + 8);
                s[nt][0] = v00 ? s[nt][0] : -1e30f;
                s[nt][1] = v01 ? s[nt][1] : -1e30f;
                s[nt][2] = v10 ? s[nt][2] : -1e30f;
                s[nt][3] = v11 ? s[nt][3] : -1e30f;
                mx0 = fmaxf(mx0, fmaxf(s[nt][0], s[nt][1]));
                mx1 = fmaxf(mx1, fmaxf(s[nt][2], s[nt][3]));
            }
            mx0 = fmaxf(mx0, __shfl_xor_sync(0xffffffffu, mx0, 1));
            mx0 = fmaxf(mx0, __shfl_xor_sync(0xffffffffu, mx0, 2));
            mx1 = fmaxf(mx1, __shfl_xor_sync(0xffffffffu, mx1, 1));
            mx1 = fmaxf(mx1, __shfl_xor_sync(0xffffffffu, mx1, 2));

            float mn0 = fmaxf(m0, mx0);
            float mn1 = fmaxf(m1, mx1);
            float al0 = ex2(m0 - mn0);
            float al1 = ex2(m1 - mn1);
            float ls0 = 0.f, ls1 = 0.f;
#pragma unroll
            for (int nt = 0; nt < 8; nt++) {
                s[nt][0] = ex2(s[nt][0] - mn0); ls0 += s[nt][0];
                s[nt][1] = ex2(s[nt][1] - mn0); ls0 += s[nt][1];
                s[nt][2] = ex2(s[nt][2] - mn1); ls1 += s[nt][2];
                s[nt][3] = ex2(s[nt][3] - mn1); ls1 += s[nt][3];
            }
            ls0 += __shfl_xor_sync(0xffffffffu, ls0, 1);
            ls0 += __shfl_xor_sync(0xffffffffu, ls0, 2);
            ls1 += __shfl_xor_sync(0xffffffffu, ls1, 1);
            ls1 += __shfl_xor_sync(0xffffffffu, ls1, 2);

            l0 = l0 * al0 + ls0;
            l1 = l1 * al1 + ls1;
            m0 = mn0;
            m1 = mn1;
#pragma unroll
            for (int nt = 0; nt < 8; nt++) {
                o[nt][0] *= al0; o[nt][1] *= al0;
                o[nt][2] *= al1; o[nt][3] *= al1;
            }
        }

        __syncthreads();

        if (wactive) {
#pragma unroll
            for (int nt = 0; nt < 8; nt++) {
                int wc = nt * 4 + tig;
                Pw[grp * 36 + wc]       = f2h2(s[nt][0], s[nt][1]);
                Pw[(grp + 8) * 36 + wc] = f2h2(s[nt][2], s[nt][3]);
            }
            __syncwarp();

#pragma unroll
            for (int ks = 0; ks < 4; ks++) {
                unsigned a[4];
                int k = ks * 8 + tig;
                a[0] = Pw[grp * 36 + k];
                a[1] = Pw[(grp + 8) * 36 + k];
                a[2] = Pw[grp * 36 + k + 4];
                a[3] = Pw[(grp + 8) * 36 + k + 4];
#pragma unroll
                for (int nt = 0; nt < 8; nt++) {
                    unsigned bb[2];
                    bb[0] = Vt[(nt * 8 + grp) * 36 + k];
                    bb[1] = Vt[(nt * 8 + grp) * 36 + k + 4];
                    mma_fp16(o[nt], a, bb);
                }
            }
        }
    }

    // ---- epilogue: normalize, write concat [B,S,H*64] as fp16 ----
    int g0 = it * 128 + qr0;
    int g1 = g0 + 8;
    int rv0 = mask[b * S_LEN + g0];
    int rv1 = mask[b * S_LEN + g1];
    float inv0 = (rv0 != 0 && m0 > -1e29f) ? (1.f / l0) : 0.f;
    float inv1 = (rv1 != 0 && m1 > -1e29f) ? (1.f / l1) : 0.f;
    size_t ro0 = ((size_t)b * S_LEN + g0) * DM + h * 64;
    size_t ro1 = ((size_t)b * S_LEN + g1) * DM + h * 64;
#pragma unroll
    for (int nt = 0; nt < 8; nt++) {
        int cc = nt * 8 + 2 * tig;
        *(unsigned*)&Oc[ro0 + cc] = f2h2(o[nt][0] * inv0, o[nt][1] * inv0);
        *(unsigned*)&Oc[ro1 + cc] = f2h2(o[nt][2] * inv1, o[nt][3] * inv1);
    }
}

// ---------------- host ------------------------------------------------------
extern "C" void kernel_launch(void* const* d_in, const int* in_sizes, int n_in,
                              void* d_out, int out_size)
{
    const float* x    = (const float*)d_in[0];
    const int*   mask = (const int*)  d_in[1];
    const float* Wq   = (const float*)d_in[2];
    const float* bq   = (const float*)d_in[3];
    const float* Wk   = (const float*)d_in[4];
    const float* bk   = (const float*)d_in[5];
    const float* Wv   = (const float*)d_in[6];
    const float* bv   = (const float*)d_in[7];
    const float* Wo   = (const float*)d_in[8];
    const float* bo   = (const float*)d_in[9];
    float* out = (float*)d_out;

    float *qp, *kp, *vp;
    __half* cph;
    cudaGetSymbolAddress((void**)&qp, g_q);
    cudaGetSymbolAddress((void**)&kp, g_k);
    cudaGetSymbolAddress((void**)&vp, g_v);
    cudaGetSymbolAddress((void**)&cph, g_cath);

    static int attr_set = 0;
    size_t asmem = (size_t)ASMEM_WORDS * 4;   // 55552 B
    if (!attr_set) {
        cudaFuncSetAttribute(attn_tc, cudaFuncAttributeMaxDynamicSharedMemorySize, (int)asmem);
        cudaFuncSetAttribute(gemm_qkv, cudaFuncAttributeMaxDynamicSharedMemorySize, GEMM_SMEM);
        cudaFuncSetAttribute(gemm_out, cudaFuncAttributeMaxDynamicSharedMemorySize, GEMM_SMEM);
        attr_set = 1;
    }

    cvt_all<<<4096, 256>>>(x, Wq, Wk, Wv, Wo);

    dim3 gqkv(DM / 128, M_TOT / 128, 3);   // (8, 32, 3)
    gemm_qkv<<<gqkv, 256, GEMM_SMEM>>>(bq, qp, bk, kp, bv, vp);

    dim3 gattn(S_LEN / 128, HEADS, BATCH);  // (16, 16, 2)
    attn_tc<<<gattn, 256, asmem>>>(qp, kp, vp, mask, cph);

    dim3 ggemm(DM / 128, M_TOT / 128);     // (8, 32)
    gemm_out<<<ggemm, 256, GEMM_SMEM>>>(bo, out);
}

// round 17
// speedup vs baseline: 1.8222x; 1.0002x over previous
#include <cuda_runtime.h>
#include <cuda_fp16.h>
#include <cstdint>
#include <math.h>

#define BATCH   2
#define S_LEN   2048
#define HEADS   16
#define HD      64
#define DM      1024
#define M_TOT   (BATCH * S_LEN)          // 4096

// ---------------- scratch (device globals: allocation-free) ----------------
__device__ float  g_q[BATCH * HEADS * S_LEN * HD];   // [B,H,S,64] fp32
__device__ float  g_k[BATCH * HEADS * S_LEN * HD];
__device__ float  g_v[BATCH * HEADS * S_LEN * HD];
__device__ __half g_xh [M_TOT * DM];                 // fp16 copies of inputs
__device__ __half g_wqh[DM * DM];
__device__ __half g_wkh[DM * DM];
__device__ __half g_wvh[DM * DM];
__device__ __half g_woh[DM * DM];
__device__ __half g_cath[M_TOT * DM];                // attn output concat (fp16)

// ---------------- helpers ---------------------------------------------------
__device__ __forceinline__ unsigned f2h2(float x, float y) {
    __half2 h = __floats2half2_rn(x, y);   // low = x, high = y
    return *reinterpret_cast<unsigned*>(&h);
}

__device__ __forceinline__ void mma_fp16(float* c, const unsigned* a, const unsigned* b) {
    asm volatile(
        "mma.sync.aligned.m16n8k16.row.col.f32.f16.f16.f32 "
        "{%0,%1,%2,%3}, {%4,%5,%6,%7}, {%8,%9}, {%0,%1,%2,%3};\n"
        : "+f"(c[0]), "+f"(c[1]), "+f"(c[2]), "+f"(c[3])
        : "r"(a[0]), "r"(a[1]), "r"(a[2]), "r"(a[3]), "r"(b[0]), "r"(b[1]));
}

__device__ __forceinline__ float ex2(float x) {
    float r;
    asm("ex2.approx.f32 %0, %1;" : "=f"(r) : "f"(x));
    return r;
}

__device__ __forceinline__ void cp16(uint32_t dst, const void* src) {
    asm volatile("cp.async.cg.shared.global [%0], [%1], 16;" :: "r"(dst), "l"(src));
}
__device__ __forceinline__ void cp_commit() {
    asm volatile("cp.async.commit_group;" ::: "memory");
}
template <int N>
__device__ __forceinline__ void cp_wait() {
    asm volatile("cp.async.wait_group %0;" :: "n"(N) : "memory");
}

// ---------------- fp16 pre-convert ------------------------------------------
__global__ __launch_bounds__(256) void cvt_all(
    const float* __restrict__ x,
    const float* __restrict__ wq, const float* __restrict__ wk,
    const float* __restrict__ wv, const float* __restrict__ wo)
{
    int i = blockIdx.x * 256 + threadIdx.x;       // float4 index, 0..1048575
    float4 v = *(const float4*)(x + 4 * (size_t)i);
    *(uint2*)((__half*)g_xh + 4 * (size_t)i) =
        make_uint2(f2h2(v.x, v.y), f2h2(v.z, v.w));
    if (i < 262144) {
        float4 a = *(const float4*)(wq + 4 * (size_t)i);
        *(uint2*)((__half*)g_wqh + 4 * (size_t)i) = make_uint2(f2h2(a.x, a.y), f2h2(a.z, a.w));
        float4 b = *(const float4*)(wk + 4 * (size_t)i);
        *(uint2*)((__half*)g_wkh + 4 * (size_t)i) = make_uint2(f2h2(b.x, b.y), f2h2(b.z, b.w));
        float4 c = *(const float4*)(wv + 4 * (size_t)i);
        *(uint2*)((__half*)g_wvh + 4 * (size_t)i) = make_uint2(f2h2(c.x, c.y), f2h2(c.z, c.w));
        float4 d = *(const float4*)(wo + 4 * (size_t)i);
        *(uint2*)((__half*)g_woh + 4 * (size_t)i) = make_uint2(f2h2(d.x, d.y), f2h2(d.z, d.w));
    }
}

// ---------------- fp16 GEMM with cp.async pipeline ---------------------------
// C[M,N] = A[M,K]*W[N,K]^T + bias; A,W fp16 in gmem; CTA 128x128, BK=64 halfs,
// 16 chunks, 3-stage cp.async pipeline, 8 warps (2x4), warp tile 64x32.
#define LDW 36                          // half2-words per smem row (32 data + 4 pad)
#define TILEB (128 * LDW * 4)           // bytes per operand tile buffer (18432)
#define STAGES 3
#define GEMM_SMEM (STAGES * 2 * TILEB)  // 110592 bytes
#define NCHUNK 16

__device__ __forceinline__ void gemm_issue_chunk(
    uint32_t sb, int stage, int kt,
    const __half* __restrict__ A, const __half* __restrict__ W,
    int bm, int bn, int tid)
{
    uint32_t abase = sb + stage * 2 * TILEB;
    uint32_t wbase = abase + TILEB;
#pragma unroll
    for (int u = 0; u < 4; u++) {
        int seg = tid + 256 * u;          // 0..1023
        int row = seg >> 3;               // 0..127
        int sc  = seg & 7;                // 16B segment in row
        uint32_t doff = (uint32_t)(row * LDW + sc * 4) * 4;
        cp16(abase + doff, A + (size_t)(bm + row) * DM + kt * 64 + sc * 8);
        cp16(wbase + doff, W + (size_t)(bn + row) * DM + kt * 64 + sc * 8);
    }
}

__device__ __forceinline__ void gemm_body(
    const __half* __restrict__ A, const __half* __restrict__ W,
    const float* __restrict__ bias, float* __restrict__ C, int scatter)
{
    extern __shared__ __align__(16) char gsm[];
    uint32_t sb = (uint32_t)__cvta_generic_to_shared(gsm);

    const int tid  = threadIdx.x;
    const int lane = tid & 31;
    const int wid  = tid >> 5;
    const int wm   = wid >> 2;
    const int wn   = wid & 3;
    const int bm   = blockIdx.y * 128;
    const int bn   = blockIdx.x * 128;
    const int grp  = lane >> 2;
    const int tig  = lane & 3;

    float c[4][4][4];
#pragma unroll
    for (int i = 0; i < 4; i++)
#pragma unroll
        for (int j = 0; j < 4; j++)
#pragma unroll
            for (int r = 0; r < 4; r++) c[i][j][r] = 0.f;

    // prologue: issue STAGES-1 chunks
#pragma unroll
    for (int s = 0; s < STAGES - 1; s++) {
        gemm_issue_chunk(sb, s, s, A, W, bm, bn, tid);
        cp_commit();
    }

    for (int kt = 0; kt < NCHUNK; kt++) {
        cp_wait<STAGES - 2>();            // chunk kt arrived
        __syncthreads();                  // visible to all; prior mma on reused buf done

        // issue chunk kt+STAGES-1 into its buffer
        if (kt + STAGES - 1 < NCHUNK)
            gemm_issue_chunk(sb, (kt + STAGES - 1) % STAGES, kt + STAGES - 1, A, W, bm, bn, tid);
        cp_commit();                      // always commit (may be empty group)

        const unsigned* As = (const unsigned*)(gsm + (kt % STAGES) * 2 * TILEB);
        const unsigned* Ws = (const unsigned*)(gsm + (kt % STAGES) * 2 * TILEB + TILEB);

#pragma unroll
        for (int ks = 0; ks < 4; ks++) {
            unsigned b[4][2];
#pragma unroll
            for (int j = 0; j < 4; j++) {
                int n = wn * 32 + j * 8 + grp;
                int k = ks * 8 + tig;
                b[j][0] = Ws[n * LDW + k];
                b[j][1] = Ws[n * LDW + k + 4];
            }
#pragma unroll
            for (int i = 0; i < 4; i++) {
                unsigned a[4];
                int m = wm * 64 + i * 16 + grp;
                int k = ks * 8 + tig;
                a[0] = As[m * LDW + k];
                a[1] = As[(m + 8) * LDW + k];
                a[2] = As[m * LDW + k + 4];
                a[3] = As[(m + 8) * LDW + k + 4];
#pragma unroll
                for (int j = 0; j < 4; j++)
                    mma_fp16(c[i][j], a, b[j]);
            }
        }
        __syncthreads();                  // all warps done with buf kt%STAGES
    }

    // epilogue: bias + store fp32
#pragma unroll
    for (int j = 0; j < 4; j++) {
        int n0 = bn + wn * 32 + j * 8 + 2 * tig;
        float bia0 = bias[n0];
        float bia1 = bias[n0 + 1];
#pragma unroll
        for (int i = 0; i < 4; i++) {
            int m0 = bm + wm * 64 + i * 16 + grp;
            float2 v0 = make_float2(c[i][j][0] + bia0, c[i][j][1] + bia1);
            float2 v1 = make_float2(c[i][j][2] + bia0, c[i][j][3] + bia1);
            if (scatter) {
                int h = n0 >> 6, d = n0 & 63;
                int b0 = m0 >> 11, s0 = m0 & 2047;
                int b1 = (m0 + 8) >> 11, s1 = (m0 + 8) & 2047;
                *(float2*)&C[(((size_t)b0 * HEADS + h) * S_LEN + s0) * HD + d] = v0;
                *(float2*)&C[(((size_t)b1 * HEADS + h) * S_LEN + s1) * HD + d] = v1;
            } else {
                *(float2*)&C[(size_t)m0 * DM + n0] = v0;
                *(float2*)&C[(size_t)(m0 + 8) * DM + n0] = v1;
            }
        }
    }
}

__global__ __launch_bounds__(256) void gemm_qkv(
    const float* __restrict__ bq, float* __restrict__ Oq,
    const float* __restrict__ bk, float* __restrict__ Ok,
    const float* __restrict__ bv, float* __restrict__ Ov)
{
    int z = blockIdx.z;
    const __half* W = (z == 0) ? (const __half*)g_wqh : (z == 1) ? (const __half*)g_wkh
                                                                 : (const __half*)g_wvh;
    const float* bb = (z == 0) ? bq : (z == 1) ? bk : bv;
    float* O = (z == 0) ? Oq : (z == 1) ? Ok : Ov;
    gemm_body((const __half*)g_xh, W, bb, O, 1);
}

__global__ __launch_bounds__(256) void gemm_out(
    const float* __restrict__ bias, float* __restrict__ C)
{
    gemm_body((const __half*)g_cath, (const __half*)g_woh, bias, C, 0);
}

// ---------------- fp16 tensor-core flash attention --------------------------
// grid (S/128, H, B), 256 threads = 8 warps; warp w owns q-rows [16w,16w+16).
#define QS_OFF 0
#define KS_OFF 4608
#define VT_OFF 6912
#define PS_OFF 9216
#define CM_OFF 13824
#define ASMEM_WORDS 13888

__global__ __launch_bounds__(256) void attn_tc(
    const float* __restrict__ Qb, const float* __restrict__ Kb,
    const float* __restrict__ Vb, const int* __restrict__ mask,
    __half* __restrict__ Oc)
{
    extern __shared__ __align__(16) unsigned smw[];
    unsigned* Qs = smw + QS_OFF;
    unsigned* Ks = smw + KS_OFF;
    unsigned* Vt = smw + VT_OFF;
    unsigned* Ps = smw + PS_OFF;
    float*    Vn = (float*)(smw + PS_OFF);
    int*      cm = (int*)(smw + CM_OFF);

    const int it  = blockIdx.x;
    const int h   = blockIdx.y;
    const int b   = blockIdx.z;
    const int tid = threadIdx.x;
    const int w    = tid >> 5;
    const int lane = tid & 31;
    const int grp  = lane >> 2;
    const int tig  = lane & 3;

    const size_t bh = ((size_t)b * HEADS + h) * S_LEN * HD;
    const float qscale = 0.125f * 1.4426950408889634f;

    for (int e = tid; e < 1024; e += 256) {
        int r = e >> 3, wc = (e & 7) << 2;
        const float* src = Qb + bh + (size_t)(it * 128 + r) * HD + 2 * wc;
        float4 f0 = *(const float4*)(src);
        float4 f1 = *(const float4*)(src + 4);
        *(uint4*)&Qs[r * 36 + wc] = make_uint4(
            f2h2(f0.x * qscale, f0.y * qscale), f2h2(f0.z * qscale, f0.w * qscale),
            f2h2(f1.x * qscale, f1.y * qscale), f2h2(f1.z * qscale, f1.w * qscale));
    }

    const int qr0 = 16 * w + grp;
    const int qbase0 = qr0 * 36;
    const int qbase1 = qbase0 + 8 * 36;
    unsigned* Pw = Ps + w * 576;

    float m0 = -1e30f, m1 = -1e30f, l0 = 0.f, l1 = 0.f;
    float o[8][4];
#pragma unroll
    for (int nt = 0; nt < 8; nt++)
#pragma unroll
        for (int r = 0; r < 4; r++) o[nt][r] = 0.f;

    const int njt = 2 * it + 2;

    for (int jt = 0; jt < njt; jt++) {
        __syncthreads();

        for (int e = tid; e < 512; e += 256) {
            int r = e >> 3, wc = (e & 7) << 2;
            const float* src = Kb + bh + (size_t)(jt * 64 + r) * HD + 2 * wc;
            float4 f0 = *(const float4*)(src);
            float4 f1 = *(const float4*)(src + 4);
            *(uint4*)&Ks[r * 36 + wc] = make_uint4(
                f2h2(f0.x, f0.y), f2h2(f0.z, f0.w),
                f2h2(f1.x, f1.y), f2h2(f1.z, f1.w));
        }
        for (int e = tid; e < 1024; e += 256) {
            int r = e >> 4, c = (e & 15) << 2;
            float4 vv = *(const float4*)(Vb + bh + (size_t)(jt * 64 + r) * HD + c);
            float* vn = &Vn[r * 65 + c];
            vn[0] = vv.x; vn[1] = vv.y; vn[2] = vv.z; vn[3] = vv.w;
        }
        if (tid < 64) cm[tid] = mask[b * S_LEN + jt * 64 + tid];
        __syncthreads();

        const int off = jt * 64 - it * 128;
        const bool band = (off >= 0);
        const bool wactive = !(off == 64 && w < 4);

        float s[8][4];
        if (wactive) {
#pragma unroll
            for (int nt = 0; nt < 8; nt++)
#pragma unroll
                for (int r = 0; r < 4; r++) s[nt][r] = 0.f;

#pragma unroll
            for (int ks = 0; ks < 4; ks++) {
                unsigned a[4];
                int k = ks * 8 + tig;
                a[0] = Qs[qbase0 + k];
                a[1] = Qs[qbase1 + k];
                a[2] = Qs[qbase0 + k + 4];
                a[3] = Qs[qbase1 + k + 4];
#pragma unroll
                for (int nt = 0; nt < 8; nt++) {
                    unsigned bb[2];
                    bb[0] = Ks[(nt * 8 + grp) * 36 + k];
                    bb[1] = Ks[(nt * 8 + grp) * 36 + k + 4];
                    mma_fp16(s[nt], a, bb);
                }
            }
        }

        {
            int d  = tid >> 2;
            int kb = (tid & 3) << 3;
#pragma unroll
            for (int i = 0; i < 8; i++) {
                int kp = kb + i;
                Vt[d * 36 + kp] = f2h2(Vn[(2 * kp) * 65 + d], Vn[(2 * kp + 1) * 65 + d]);
            }
        }

        if (wactive) {
            float mx0 = -1e30f, mx1 = -1e30f;
#pragma unroll
            for (int nt = 0; nt < 8; nt++) {
                int lc0 = nt * 8 + 2 * tig;
                int lc1 = lc0 + 1;
                bool c0 = cm[lc0] != 0;
                bool c1 = cm[lc1] != 0;
                bool v00 = c0 && (!band || lc0 + off <= qr0);
                bool v01 = c1 && (!band || lc1 + off <= qr0);
                bool v10 = c0 && (!band || lc0 + off <= qr0 + 8);
                bool v11 = c1 && (!band || lc1 + off <= qr0 + 8);
                s[nt][0] = v00 ? s[nt][0] : -1e30f;
                s[nt][1] = v01 ? s[nt][1] : -1e30f;
                s[nt][2] = v10 ? s[nt][2] : -1e30f;
                s[nt][3] = v11 ? s[nt][3] : -1e30f;
                mx0 = fmaxf(mx0, fmaxf(s[nt][0], s[nt][1]));
                mx1 = fmaxf(mx1, fmaxf(s[nt][2], s[nt][3]));
            }
            mx0 = fmaxf(mx0, __shfl_xor_sync(0xffffffffu, mx0, 1));
            mx0 = fmaxf(mx0, __shfl_xor_sync(0xffffffffu, mx0, 2));
            mx1 = fmaxf(mx1, __shfl_xor_sync(0xffffffffu, mx1, 1));
            mx1 = fmaxf(mx1, __shfl_xor_sync(0xffffffffu, mx1, 2));

            float mn0 = fmaxf(m0, mx0);
            float mn1 = fmaxf(m1, mx1);
            float al0 = ex2(m0 - mn0);
            float al1 = ex2(m1 - mn1);
            float ls0 = 0.f, ls1 = 0.f;
#pragma unroll
            for (int nt = 0; nt < 8; nt++) {
                s[nt][0] = ex2(s[nt][0] - mn0); ls0 += s[nt][0];
                s[nt][1] = ex2(s[nt][1] - mn0); ls0 += s[nt][1];
                s[nt][2] = ex2(s[nt][2] - mn1); ls1 += s[nt][2];
                s[nt][3] = ex2(s[nt][3] - mn1); ls1 += s[nt][3];
            }
            ls0 += __shfl_xor_sync(0xffffffffu, ls0, 1);
            ls0 += __shfl_xor_sync(0xffffffffu, ls0, 2);
            ls1 += __shfl_xor_sync(0xffffffffu, ls1, 1);
            ls1 += __shfl_xor_sync(0xffffffffu, ls1, 2);

            l0 = l0 * al0 + ls0;
            l1 = l1 * al1 + ls1;
            m0 = mn0;
            m1 = mn1;
#pragma unroll
            for (int nt = 0; nt < 8; nt++) {
                o[nt][0] *= al0; o[nt][1] *= al0;
                o[nt][2] *= al1; o[nt][3] *= al1;
            }
        }

        __syncthreads();

        if (wactive) {
#pragma unroll
            for (int nt = 0; nt < 8; nt++) {
                int wc = nt * 4 + tig;
                Pw[grp * 36 + wc]       = f2h2(s[nt][0], s[nt][1]);
                Pw[(grp + 8) * 36 + wc] = f2h2(s[nt][2], s[nt][3]);
            }
            __syncwarp();

#pragma unroll
            for (int ks = 0; ks < 4; ks++) {
                unsigned a[4];
                int k = ks * 8 + tig;
                a[0] = Pw[grp * 36 + k];
                a[1] = Pw[(grp + 8) * 36 + k];
                a[2] = Pw[grp * 36 + k + 4];
                a[3] = Pw[(grp + 8) * 36 + k + 4];
#pragma unroll
                for (int nt = 0; nt < 8; nt++) {
                    unsigned bb[2];
                    bb[0] = Vt[(nt * 8 + grp) * 36 + k];
                    bb[1] = Vt[(nt * 8 + grp) * 36 + k + 4];
                    mma_fp16(o[nt], a, bb);
                }
            }
        }
    }

    // ---- epilogue: normalize, write concat [B,S,H*64] as fp16 ----
    int g0 = it * 128 + qr0;
    int g1 = g0 + 8;
    int rv0 = mask[b * S_LEN + g0];
    int rv1 = mask[b * S_LEN + g1];
    float inv0 = (rv0 != 0 && m0 > -1e29f) ? (1.f / l0) : 0.f;
    float inv1 = (rv1 != 0 && m1 > -1e29f) ? (1.f / l1) : 0.f;
    size_t ro0 = ((size_t)b * S_LEN + g0) * DM + h * 64;
    size_t ro1 = ((size_t)b * S_LEN + g1) * DM + h * 64;
#pragma unroll
    for (int nt = 0; nt < 8; nt++) {
        int cc = nt * 8 + 2 * tig;
        *(unsigned*)&Oc[ro0 + cc] = f2h2(o[nt][0] * inv0, o[nt][1] * inv0);
        *(unsigned*)&Oc[ro1 + cc] = f2h2(o[nt][2] * inv1, o[nt][3] * inv1);
    }
}

// ---------------- host ------------------------------------------------------
extern "C" void kernel_launch(void* const* d_in, const int* in_sizes, int n_in,
                              void* d_out, int out_size)
{
    const float* x    = (const float*)d_in[0];
    const int*   mask = (const int*)  d_in[1];
    const float* Wq   = (const float*)d_in[2];
    const float* bq   = (const float*)d_in[3];
    const float* Wk   = (const float*)d_in[4];
    const float* bk   = (const float*)d_in[5];
    const float* Wv   = (const float*)d_in[6];
    const float* bv   = (const float*)d_in[7];
    const float* Wo   = (const float*)d_in[8];
    const float* bo   = (const float*)d_in[9];
    float* out = (float*)d_out;

    float *qp, *kp, *vp;
    __half* cph;
    cudaGetSymbolAddress((void**)&qp, g_q);
    cudaGetSymbolAddress((void**)&kp, g_k);
    cudaGetSymbolAddress((void**)&vp, g_v);
    cudaGetSymbolAddress((void**)&cph, g_cath);

    static int attr_set = 0;
    size_t asmem = (size_t)ASMEM_WORDS * 4;   // 55552 B
    if (!attr_set) {
        cudaFuncSetAttribute(attn_tc, cudaFuncAttributeMaxDynamicSharedMemorySize, (int)asmem);
        cudaFuncSetAttribute(gemm_qkv, cudaFuncAttributeMaxDynamicSharedMemorySize, GEMM_SMEM);
        cudaFuncSetAttribute(gemm_out, cudaFuncAttributeMaxDynamicSharedMemorySize, GEMM_SMEM);
        attr_set = 1;
    }

    cvt_all<<<4096, 256>>>(x, Wq, Wk, Wv, Wo);

    dim3 gqkv(DM / 128, M_TOT / 128, 3);   // (8, 32, 3)
    gemm_qkv<<<gqkv, 256, GEMM_SMEM>>>(bq, qp, bk, kp, bv, vp);

    dim3 gattn(S_LEN / 128, HEADS, BATCH);  // (16, 16, 2)
    attn_tc<<<gattn, 256, asmem>>>(qp, kp, vp, mask, cph);

    dim3 ggemm(DM / 128, M_TOT / 128);     // (8, 32)
    gemm_out<<<ggemm, 256, GEMM_SMEM>>>(bo, out);
}